// round 11
// baseline (speedup 1.0000x reference)
#include <cuda_runtime.h>
#include <cuda_bf16.h>
#include <cuda_fp16.h>
#include <cstdint>

#define TQ 64
#define TK 128
#define BATCH 32
#define N_DIM 1024
#define MQ (TQ*BATCH)   /* 2048 */
#define MK (TK*BATCH)   /* 4096 */

// ---------------- scratch (no allocations allowed) ----------------
__device__ __half g_pq_h[MQ*N_DIM];
__device__ __half g_pk_h[MK*N_DIM];
__device__ __nv_bfloat16 g_qb[MQ*N_DIM];
__device__ __nv_bfloat16 g_kb[MK*N_DIM];
__device__ __nv_bfloat16 g_wqb[N_DIM*N_DIM];
__device__ __nv_bfloat16 g_wkb[N_DIM*N_DIM];
__device__ __half2 g_v_h2[N_DIM/2];
__device__ __half2 g_bias_h2[N_DIM/2];
__device__ float g_sraw[MQ*TK];

// ---------------- helpers ----------------
__device__ __forceinline__ __half2 tanh2(__half2 x){
    __half2 y;
    asm("tanh.approx.f16x2 %0, %1;"
        : "=r"(*(uint32_t*)&y) : "r"(*(uint32_t*)&x));
    return y;
}

__device__ __forceinline__ void cp16(void* dst, const void* src){
    uint32_t d = (uint32_t)__cvta_generic_to_shared(dst);
    asm volatile("cp.async.ca.shared.global [%0], [%1], 16;" :: "r"(d), "l"(src));
}

// XOR swizzle for 64B (32-bf16) rows: 16B chunk index ^= (row>>1)&3.
__device__ __forceinline__ uint32_t swz(int row, int bytecol){
    return (uint32_t)(row*64 + ((((bytecol>>4) ^ ((row>>1)&3))<<4) | (bytecol & 15)));
}

__device__ __forceinline__ void ldm_x4(uint32_t* r, uint32_t addr){
    asm volatile("ldmatrix.sync.aligned.m8n8.x4.shared.b16 {%0,%1,%2,%3}, [%4];"
                 : "=r"(r[0]), "=r"(r[1]), "=r"(r[2]), "=r"(r[3]) : "r"(addr));
}

// ---------------- fused f32 -> bf16 conversion (one launch, packed stores) ----------------
__global__ void __launch_bounds__(256) conv_all_kernel(const float* __restrict__ q,
                                                       const float* __restrict__ k,
                                                       const float* __restrict__ wq,
                                                       const float* __restrict__ wk){
    const int nq = MQ*N_DIM/4, nk = MK*N_DIM/4, nw = N_DIM*N_DIM/4;
    const int total = nq + nk + 2*nw;
    int i = blockIdx.x*blockDim.x + threadIdx.x;
    int stride = gridDim.x*blockDim.x;
    for (; i < total; i += stride){
        const float* src; __nv_bfloat16* dst; int off;
        if (i < nq)            { src = q;  dst = g_qb;  off = i; }
        else if (i < nq+nk)    { src = k;  dst = g_kb;  off = i - nq; }
        else if (i < nq+nk+nw) { src = wq; dst = g_wqb; off = i - nq - nk; }
        else                   { src = wk; dst = g_wkb; off = i - nq - nk - nw; }
        float4 v = ((const float4*)src)[off];
        __nv_bfloat162 lo = __floats2bfloat162_rn(v.x, v.y);
        __nv_bfloat162 hi = __floats2bfloat162_rn(v.z, v.w);
        uint2 u; u.x = *(uint32_t*)&lo; u.y = *(uint32_t*)&hi;
        ((uint2*)dst)[off] = u;
    }
}

// ---------------- normalized attention vector v + bias, packed f16x2 ----------------
__global__ void prep_v_kernel(const float* __restrict__ la, const float* __restrict__ ns,
                              const float* __restrict__ bias){
    __shared__ float red[256];
    int t = threadIdx.x;
    float s = 0.f;
    for (int u = t; u < N_DIM; u += 256){ float x = la[u]; s += x*x; }
    red[t] = s; __syncthreads();
    for (int off = 128; off; off >>= 1){
        if (t < off) red[t] += red[t+off];
        __syncthreads();
    }
    float scale = ns[0] * rsqrtf(red[0]);
    for (int h = t; h < N_DIM/2; h += 256){
        g_v_h2[h]    = __floats2half2_rn(la[2*h]*scale, la[2*h+1]*scale);
        g_bias_h2[h] = __floats2half2_rn(bias[2*h], bias[2*h+1]);
    }
}

// ---------------- bf16 mma.sync GEMM, f16 output (unchanged from R9 PASS) ----------------
__global__ void __launch_bounds__(256) gemm_kernel(){
    __shared__ __align__(16) __nv_bfloat16 sAB[3][2][128][32];  // 49152 B

    const __nv_bfloat16* A; const __nv_bfloat16* B; __half* C;
    int m0;
    if (blockIdx.x < 16){ A = g_qb; B = g_wqb; C = g_pq_h; m0 = blockIdx.x * 128; }
    else                { A = g_kb; B = g_wkb; C = g_pk_h; m0 = (blockIdx.x - 16) * 128; }

    const int K = 1024, Nn = 1024, NIT = K/32;
    int t = threadIdx.x;
    int n0 = blockIdx.y * 128;
    int w = t >> 5, lane = t & 31;
    int wm = (w >> 2) * 64, wn = (w & 3) * 32;
    int grp = lane >> 2, tg = lane & 3;

    float acc[4][4][4];
    #pragma unroll
    for (int i=0;i<4;i++)
        #pragma unroll
        for (int j=0;j<4;j++)
            #pragma unroll
            for (int c=0;c<4;c++) acc[i][j][c] = 0.f;

    uint32_t smem_u32 = (uint32_t)__cvta_generic_to_shared(&sAB[0][0][0][0]);

    int r0c = t >> 2,        ch0 = t & 3;
    int r1c = (t+256) >> 2,  ch1 = t & 3;
    const __nv_bfloat16* gA0 = A + (size_t)(m0 + r0c)*K + ch0*8;
    const __nv_bfloat16* gA1 = A + (size_t)(m0 + r1c)*K + ch1*8;
    const __nv_bfloat16* gB0 = B + (size_t)(n0 + r0c)*K + ch0*8;
    const __nv_bfloat16* gB1 = B + (size_t)(n0 + r1c)*K + ch1*8;
    uint32_t dA0 = swz(r0c, ch0*16), dA1 = swz(r1c, ch1*16);

    int a_row = (lane & 15);
    int a_bc  = (lane >> 4) << 4;
    int b_row = (lane & 7) + ((lane >> 4) << 3);
    int b_bc  = ((lane >> 3) & 1) << 4;

    #pragma unroll
    for (int s = 0; s < 2; s++){
        char* sa = (char*)&sAB[s][0][0][0];
        char* sb = (char*)&sAB[s][1][0][0];
        cp16(sa + dA0, gA0 + s*32); cp16(sa + dA1, gA1 + s*32);
        cp16(sb + dA0, gB0 + s*32); cp16(sb + dA1, gB1 + s*32);
        asm volatile("cp.async.commit_group;");
    }

    for (int i = 0; i < NIT; i++){
        if (i + 1 < NIT) asm volatile("cp.async.wait_group 1;");
        else             asm volatile("cp.async.wait_group 0;");
        __syncthreads();

        int buf = i % 3;
        uint32_t sA = smem_u32 + buf*16384;
        uint32_t sB = sA + 8192;

        #pragma unroll
        for (int c = 0; c < 2; c++){
            uint32_t a[4][4], bfr[2][4];
            #pragma unroll
            for (int ii=0;ii<4;ii++)
                ldm_x4(a[ii], sA + swz(wm + ii*16 + a_row, c*32 + a_bc));
            #pragma unroll
            for (int jp=0;jp<2;jp++)
                ldm_x4(bfr[jp], sB + swz(wn + jp*16 + b_row, c*32 + b_bc));
            #pragma unroll
            for (int ii=0;ii<4;ii++)
                #pragma unroll
                for (int jj=0;jj<4;jj++){
                    uint32_t b0 = bfr[jj>>1][(jj&1)*2];
                    uint32_t b1 = bfr[jj>>1][(jj&1)*2+1];
                    asm volatile(
                        "mma.sync.aligned.m16n8k16.row.col.f32.bf16.bf16.f32 "
                        "{%0,%1,%2,%3}, {%4,%5,%6,%7}, {%8,%9}, {%0,%1,%2,%3};"
                        : "+f"(acc[ii][jj][0]), "+f"(acc[ii][jj][1]),
                          "+f"(acc[ii][jj][2]), "+f"(acc[ii][jj][3])
                        : "r"(a[ii][0]), "r"(a[ii][1]), "r"(a[ii][2]), "r"(a[ii][3]),
                          "r"(b0), "r"(b1));
                }
        }

        if (i + 2 < NIT){
            int nb = (i + 2) % 3;
            char* sa = (char*)&sAB[nb][0][0][0];
            char* sb = (char*)&sAB[nb][1][0][0];
            cp16(sa + dA0, gA0 + (i+2)*32); cp16(sa + dA1, gA1 + (i+2)*32);
            cp16(sb + dA0, gB0 + (i+2)*32); cp16(sb + dA1, gB1 + (i+2)*32);
            asm volatile("cp.async.commit_group;");
        }
    }

    #pragma unroll
    for (int i=0;i<4;i++){
        int m = m0 + wm + i*16 + grp;
        #pragma unroll
        for (int j=0;j<4;j++){
            int n = n0 + wn + j*8 + tg*2;
            *(__half2*)&C[(size_t)m*Nn + n]     = __floats2half2_rn(acc[i][j][0], acc[i][j][1]);
            *(__half2*)&C[(size_t)(m+8)*Nn + n] = __floats2half2_rn(acc[i][j][2], acc[i][j][3]);
        }
    }
}

// ---------------- raw score kernel (f16x2, 8 warps/block for occupancy) ----------------
// grid (8 q-tiles of 8, 32 batches, 4 k-chunks of 32), 256 threads (8 warps).
// Warp w owns q = qt*8+w; all 8 warps share the staged pk rows.
__global__ void __launch_bounds__(256) score_raw_kernel(){
    __shared__ __align__(16) __half spk[2][4][N_DIM];  // 16 KB
    int t = threadIdx.x, w = t >> 5, lane = t & 31;
    int qt = blockIdx.x, b = blockIdx.y, kc = blockIdx.z;
    int q = qt*8 + w;
    int r = q*BATCH + b;

    // pqb2[jj*4+c] maps to half2 index 4*(lane+32*jj)+c  (matches uint4 smem loads)
    __half2 pqb2[16], vv2[16];
    {
        const uint4* pq4 = (const uint4*)(g_pq_h + (size_t)r*N_DIM);
        const uint4* bi4 = (const uint4*)g_bias_h2;
        const uint4* v4  = (const uint4*)g_v_h2;
        #pragma unroll
        for (int jj=0;jj<4;jj++){
            uint4 up = pq4[lane + 32*jj];
            uint4 ub = bi4[lane + 32*jj];
            uint4 uv = v4 [lane + 32*jj];
            const uint32_t* pp = &up.x; const uint32_t* pb = &ub.x; const uint32_t* pv = &uv.x;
            #pragma unroll
            for (int c=0;c<4;c++){
                pqb2[jj*4+c] = __hadd2(*(const __half2*)&pp[c], *(const __half2*)&pb[c]);
                vv2 [jj*4+c] = *(const __half2*)&pv[c];
            }
        }
    }

    // prologue: stage k-group 0 (4 rows x 2KB = 512 uint4, 2 per thread)
    #pragma unroll
    for (int p=0;p<2;p++){
        int f = t + p*256;
        int row = f >> 7, c16 = f & 127;
        cp16(&spk[0][row][c16*8],
             g_pk_h + (size_t)((kc*32 + row)*BATCH + b)*N_DIM + c16*8);
    }
    asm volatile("cp.async.commit_group;");

    for (int kg = 0; kg < 8; kg++){
        int cur = kg & 1;
        asm volatile("cp.async.wait_group 0;");
        __syncthreads();
        if (kg + 1 < 8){
            #pragma unroll
            for (int p=0;p<2;p++){
                int f = t + p*256;
                int row = f >> 7, c16 = f & 127;
                cp16(&spk[cur^1][row][c16*8],
                     g_pk_h + (size_t)((kc*32 + (kg+1)*4 + row)*BATCH + b)*N_DIM + c16*8);
            }
            asm volatile("cp.async.commit_group;");
        }

        float s[4];
        #pragma unroll
        for (int kk=0;kk<4;kk++){
            const uint4* sp = (const uint4*)spk[cur][kk];
            __half2 a0 = __float2half2_rn(0.f), a1 = a0, a2 = a0, a3 = a0;
            #pragma unroll
            for (int jj=0;jj<4;jj++){
                uint4 u = sp[lane + 32*jj];
                const uint32_t* pu = &u.x;
                a0 = __hfma2(vv2[jj*4+0], tanh2(__hadd2(pqb2[jj*4+0], *(const __half2*)&pu[0])), a0);
                a1 = __hfma2(vv2[jj*4+1], tanh2(__hadd2(pqb2[jj*4+1], *(const __half2*)&pu[1])), a1);
                a2 = __hfma2(vv2[jj*4+2], tanh2(__hadd2(pqb2[jj*4+2], *(const __half2*)&pu[2])), a2);
                a3 = __hfma2(vv2[jj*4+3], tanh2(__hadd2(pqb2[jj*4+3], *(const __half2*)&pu[3])), a3);
            }
            __half2 s2 = __hadd2(__hadd2(a0,a1), __hadd2(a2,a3));
            s[kk] = __low2float(s2) + __high2float(s2);
        }
        #pragma unroll
        for (int off=16; off; off>>=1){
            #pragma unroll
            for (int kk=0;kk<4;kk++)
                s[kk] += __shfl_xor_sync(0xffffffffu, s[kk], off);
        }
        // after full butterfly every lane holds chain-kk total; lane kk writes chain kk
        if (lane < 4) g_sraw[(size_t)r*TK + kc*32 + kg*4 + lane] = s[lane];
    }
}

// ---------------- softmax + context ----------------
// grid (8 q-tiles of 8, 32 batches), 256 threads. Warp w owns q = qt*8+w.
__global__ void __launch_bounds__(256) softmax_ctx_kernel(const float* __restrict__ keys,
                                                          float* __restrict__ out_ctx,
                                                          float* __restrict__ out_scores){
    __shared__ float sw[8][TK];
    int t = threadIdx.x, w = t >> 5, lane = t & 31;
    int qt = blockIdx.x, b = blockIdx.y;
    int r = (qt*8 + w)*BATCH + b;

    float sc[4];
    #pragma unroll
    for (int j=0;j<4;j++) sc[j] = g_sraw[(size_t)r*TK + lane + 32*j];
    float mx = fmaxf(fmaxf(sc[0],sc[1]), fmaxf(sc[2],sc[3]));
    #pragma unroll
    for (int off=16; off; off>>=1) mx = fmaxf(mx, __shfl_xor_sync(0xffffffffu, mx, off));
    float sum = 0.f;
    #pragma unroll
    for (int j=0;j<4;j++){ sc[j] = __expf(sc[j]-mx); sum += sc[j]; }
    #pragma unroll
    for (int off=16; off; off>>=1) sum += __shfl_xor_sync(0xffffffffu, sum, off);
    float inv = 1.f/sum;
    #pragma unroll
    for (int j=0;j<4;j++){
        float wk = sc[j]*inv;
        sw[w][lane + 32*j] = wk;
        out_scores[(size_t)r*TK + lane + 32*j] = wk;
    }
    __syncthreads();

    // context: ctx[q][nn] = sum_k w[q][k] * keys[k][b][nn]
    float4 acc[8];
    #pragma unroll
    for (int q8=0;q8<8;q8++) acc[q8] = make_float4(0.f,0.f,0.f,0.f);
    #pragma unroll 4
    for (int k=0;k<TK;k++){
        float4 kv = ((const float4*)(keys + (size_t)(k*BATCH + b)*N_DIM))[t];
        #pragma unroll
        for (int q8=0;q8<8;q8++){
            float wk = sw[q8][k];
            acc[q8].x += wk*kv.x; acc[q8].y += wk*kv.y;
            acc[q8].z += wk*kv.z; acc[q8].w += wk*kv.w;
        }
    }
    #pragma unroll
    for (int q8=0;q8<8;q8++){
        int rr = (qt*8 + q8)*BATCH + b;
        ((float4*)(out_ctx + (size_t)rr*N_DIM))[t] = acc[q8];
    }
}

// ---------------- launch ----------------
extern "C" void kernel_launch(void* const* d_in, const int* in_sizes, int n_in,
                              void* d_out, int out_size){
    const float* query = (const float*)d_in[0];
    const float* keys  = (const float*)d_in[1];
    const float* Wq    = (const float*)d_in[2];
    const float* Wk    = (const float*)d_in[3];
    const float* la    = (const float*)d_in[4];
    const float* ns    = (const float*)d_in[5];
    const float* bias  = (const float*)d_in[6];

    float* out_ctx    = (float*)d_out;
    float* out_scores = (float*)d_out + (size_t)MQ*N_DIM;

    // max smem carveout -> more resident blocks (idempotent, capture-safe host calls)
    cudaFuncSetAttribute(score_raw_kernel,
                         cudaFuncAttributePreferredSharedMemoryCarveout,
                         cudaSharedmemCarveoutMaxShared);
    cudaFuncSetAttribute(gemm_kernel,
                         cudaFuncAttributePreferredSharedMemoryCarveout,
                         cudaSharedmemCarveoutMaxShared);

    conv_all_kernel<<<2048,256>>>(query, keys, Wq, Wk);
    prep_v_kernel<<<1,256>>>(la, ns, bias);

    gemm_kernel<<<dim3(48, 8), 256>>>();

    score_raw_kernel<<<dim3(8, BATCH, 4), 256>>>();
    softmax_ctx_kernel<<<dim3(8, BATCH), 256>>>(keys, out_ctx, out_scores);
}

// round 12
// speedup vs baseline: 1.6000x; 1.6000x over previous
#include <cuda_runtime.h>
#include <cuda_bf16.h>
#include <cuda_fp16.h>
#include <cstdint>

#define TQ 64
#define TK 128
#define BATCH 32
#define N_DIM 1024
#define MQ (TQ*BATCH)   /* 2048 */
#define MK (TK*BATCH)   /* 4096 */

// ---------------- scratch (no allocations allowed) ----------------
__device__ __half g_pq_h[MQ*N_DIM];
__device__ __half g_pk_h[MK*N_DIM];
__device__ __nv_bfloat16 g_qb[MQ*N_DIM];
__device__ __nv_bfloat16 g_kb[MK*N_DIM];
__device__ __nv_bfloat16 g_wqb[N_DIM*N_DIM];
__device__ __nv_bfloat16 g_wkb[N_DIM*N_DIM];
__device__ __half2 g_v_h2[N_DIM/2];
__device__ __half2 g_bias_h2[N_DIM/2];
__device__ float g_sraw[MQ*TK];

// ---------------- helpers ----------------
__device__ __forceinline__ __half2 tanh2(__half2 x){
    __half2 y;
    asm("tanh.approx.f16x2 %0, %1;"
        : "=r"(*(uint32_t*)&y) : "r"(*(uint32_t*)&x));
    return y;
}

__device__ __forceinline__ void cp16(void* dst, const void* src){
    uint32_t d = (uint32_t)__cvta_generic_to_shared(dst);
    asm volatile("cp.async.ca.shared.global [%0], [%1], 16;" :: "r"(d), "l"(src));
}

// XOR swizzle for 64B (32-bf16) rows: 16B chunk index ^= (row>>1)&3.
__device__ __forceinline__ uint32_t swz(int row, int bytecol){
    return (uint32_t)(row*64 + ((((bytecol>>4) ^ ((row>>1)&3))<<4) | (bytecol & 15)));
}

__device__ __forceinline__ void ldm_x4(uint32_t* r, uint32_t addr){
    asm volatile("ldmatrix.sync.aligned.m8n8.x4.shared.b16 {%0,%1,%2,%3}, [%4];"
                 : "=r"(r[0]), "=r"(r[1]), "=r"(r[2]), "=r"(r[3]) : "r"(addr));
}

// ---------------- fused f32 -> bf16 conversion (one launch, packed stores) ----------------
__global__ void __launch_bounds__(256) conv_all_kernel(const float* __restrict__ q,
                                                       const float* __restrict__ k,
                                                       const float* __restrict__ wq,
                                                       const float* __restrict__ wk){
    const int nq = MQ*N_DIM/4, nk = MK*N_DIM/4, nw = N_DIM*N_DIM/4;
    const int total = nq + nk + 2*nw;
    int i = blockIdx.x*blockDim.x + threadIdx.x;
    int stride = gridDim.x*blockDim.x;
    for (; i < total; i += stride){
        const float* src; __nv_bfloat16* dst; int off;
        if (i < nq)            { src = q;  dst = g_qb;  off = i; }
        else if (i < nq+nk)    { src = k;  dst = g_kb;  off = i - nq; }
        else if (i < nq+nk+nw) { src = wq; dst = g_wqb; off = i - nq - nk; }
        else                   { src = wk; dst = g_wkb; off = i - nq - nk - nw; }
        float4 v = ((const float4*)src)[off];
        __nv_bfloat162 lo = __floats2bfloat162_rn(v.x, v.y);
        __nv_bfloat162 hi = __floats2bfloat162_rn(v.z, v.w);
        uint2 u; u.x = *(uint32_t*)&lo; u.y = *(uint32_t*)&hi;
        ((uint2*)dst)[off] = u;
    }
}

// ---------------- normalized attention vector v + bias, packed f16x2 ----------------
__global__ void prep_v_kernel(const float* __restrict__ la, const float* __restrict__ ns,
                              const float* __restrict__ bias){
    __shared__ float red[256];
    int t = threadIdx.x;
    float s = 0.f;
    for (int u = t; u < N_DIM; u += 256){ float x = la[u]; s += x*x; }
    red[t] = s; __syncthreads();
    for (int off = 128; off; off >>= 1){
        if (t < off) red[t] += red[t+off];
        __syncthreads();
    }
    float scale = ns[0] * rsqrtf(red[0]);
    for (int h = t; h < N_DIM/2; h += 256){
        g_v_h2[h]    = __floats2half2_rn(la[2*h]*scale, la[2*h+1]*scale);
        g_bias_h2[h] = __floats2half2_rn(bias[2*h], bias[2*h+1]);
    }
}

// ---------------- bf16 mma.sync GEMM, f16 output (R9 PASS version, no carveout) ----------------
__global__ void __launch_bounds__(256) gemm_kernel(){
    __shared__ __align__(16) __nv_bfloat16 sAB[3][2][128][32];  // 49152 B

    const __nv_bfloat16* A; const __nv_bfloat16* B; __half* C;
    int m0;
    if (blockIdx.x < 16){ A = g_qb; B = g_wqb; C = g_pq_h; m0 = blockIdx.x * 128; }
    else                { A = g_kb; B = g_wkb; C = g_pk_h; m0 = (blockIdx.x - 16) * 128; }

    const int K = 1024, Nn = 1024, NIT = K/32;
    int t = threadIdx.x;
    int n0 = blockIdx.y * 128;
    int w = t >> 5, lane = t & 31;
    int wm = (w >> 2) * 64, wn = (w & 3) * 32;
    int grp = lane >> 2, tg = lane & 3;

    float acc[4][4][4];
    #pragma unroll
    for (int i=0;i<4;i++)
        #pragma unroll
        for (int j=0;j<4;j++)
            #pragma unroll
            for (int c=0;c<4;c++) acc[i][j][c] = 0.f;

    uint32_t smem_u32 = (uint32_t)__cvta_generic_to_shared(&sAB[0][0][0][0]);

    int r0c = t >> 2,        ch0 = t & 3;
    int r1c = (t+256) >> 2,  ch1 = t & 3;
    const __nv_bfloat16* gA0 = A + (size_t)(m0 + r0c)*K + ch0*8;
    const __nv_bfloat16* gA1 = A + (size_t)(m0 + r1c)*K + ch1*8;
    const __nv_bfloat16* gB0 = B + (size_t)(n0 + r0c)*K + ch0*8;
    const __nv_bfloat16* gB1 = B + (size_t)(n0 + r1c)*K + ch1*8;
    uint32_t dA0 = swz(r0c, ch0*16), dA1 = swz(r1c, ch1*16);

    int a_row = (lane & 15);
    int a_bc  = (lane >> 4) << 4;
    int b_row = (lane & 7) + ((lane >> 4) << 3);
    int b_bc  = ((lane >> 3) & 1) << 4;

    #pragma unroll
    for (int s = 0; s < 2; s++){
        char* sa = (char*)&sAB[s][0][0][0];
        char* sb = (char*)&sAB[s][1][0][0];
        cp16(sa + dA0, gA0 + s*32); cp16(sa + dA1, gA1 + s*32);
        cp16(sb + dA0, gB0 + s*32); cp16(sb + dA1, gB1 + s*32);
        asm volatile("cp.async.commit_group;");
    }

    for (int i = 0; i < NIT; i++){
        if (i + 1 < NIT) asm volatile("cp.async.wait_group 1;");
        else             asm volatile("cp.async.wait_group 0;");
        __syncthreads();

        int buf = i % 3;
        uint32_t sA = smem_u32 + buf*16384;
        uint32_t sB = sA + 8192;

        #pragma unroll
        for (int c = 0; c < 2; c++){
            uint32_t a[4][4], bfr[2][4];
            #pragma unroll
            for (int ii=0;ii<4;ii++)
                ldm_x4(a[ii], sA + swz(wm + ii*16 + a_row, c*32 + a_bc));
            #pragma unroll
            for (int jp=0;jp<2;jp++)
                ldm_x4(bfr[jp], sB + swz(wn + jp*16 + b_row, c*32 + b_bc));
            #pragma unroll
            for (int ii=0;ii<4;ii++)
                #pragma unroll
                for (int jj=0;jj<4;jj++){
                    uint32_t b0 = bfr[jj>>1][(jj&1)*2];
                    uint32_t b1 = bfr[jj>>1][(jj&1)*2+1];
                    asm volatile(
                        "mma.sync.aligned.m16n8k16.row.col.f32.bf16.bf16.f32 "
                        "{%0,%1,%2,%3}, {%4,%5,%6,%7}, {%8,%9}, {%0,%1,%2,%3};"
                        : "+f"(acc[ii][jj][0]), "+f"(acc[ii][jj][1]),
                          "+f"(acc[ii][jj][2]), "+f"(acc[ii][jj][3])
                        : "r"(a[ii][0]), "r"(a[ii][1]), "r"(a[ii][2]), "r"(a[ii][3]),
                          "r"(b0), "r"(b1));
                }
        }

        if (i + 2 < NIT){
            int nb = (i + 2) % 3;
            char* sa = (char*)&sAB[nb][0][0][0];
            char* sb = (char*)&sAB[nb][1][0][0];
            cp16(sa + dA0, gA0 + (i+2)*32); cp16(sa + dA1, gA1 + (i+2)*32);
            cp16(sb + dA0, gB0 + (i+2)*32); cp16(sb + dA1, gB1 + (i+2)*32);
            asm volatile("cp.async.commit_group;");
        }
    }

    #pragma unroll
    for (int i=0;i<4;i++){
        int m = m0 + wm + i*16 + grp;
        #pragma unroll
        for (int j=0;j<4;j++){
            int n = n0 + wn + j*8 + tg*2;
            *(__half2*)&C[(size_t)m*Nn + n]     = __floats2half2_rn(acc[i][j][0], acc[i][j][1]);
            *(__half2*)&C[(size_t)(m+8)*Nn + n] = __floats2half2_rn(acc[i][j][2], acc[i][j][3]);
        }
    }
}

// ---------------- raw score kernel: f16x2 MUFU, DEFERRED reduction ----------------
// grid (16 q-tiles of 4, 32 batches, 4 k-chunks of 32), 128 threads (4 warps).
// Warp w owns q = qt*4+w. 32 f32 per-lane partials held in registers across the
// whole k-loop (NO shfl in loop); one swizzled smem transpose + 31 FADDs at the
// end, reusing the pk staging buffer (4KB/warp). Coalesced 32-lane STG.
__global__ void __launch_bounds__(128) score_raw_kernel(){
    __shared__ __align__(16) char smem_raw[2*4*N_DIM*2];  // 16 KB
    __half (*spk)[4][N_DIM] = (__half (*)[4][N_DIM])smem_raw;
    int t = threadIdx.x, w = t >> 5, lane = t & 31;
    int qt = blockIdx.x, b = blockIdx.y, kc = blockIdx.z;
    int q = qt*4 + w;
    int r = q*BATCH + b;

    // pqb2[jj*4+c] maps to half2 index 4*(lane+32*jj)+c  (matches uint4 smem loads)
    __half2 pqb2[16], vv2[16];
    {
        const uint4* pq4 = (const uint4*)(g_pq_h + (size_t)r*N_DIM);
        const uint4* bi4 = (const uint4*)g_bias_h2;
        const uint4* v4  = (const uint4*)g_v_h2;
        #pragma unroll
        for (int jj=0;jj<4;jj++){
            uint4 up = pq4[lane + 32*jj];
            uint4 ub = bi4[lane + 32*jj];
            uint4 uv = v4 [lane + 32*jj];
            const uint32_t* pp = &up.x; const uint32_t* pb = &ub.x; const uint32_t* pv = &uv.x;
            #pragma unroll
            for (int c=0;c<4;c++){
                pqb2[jj*4+c] = __hadd2(*(const __half2*)&pp[c], *(const __half2*)&pb[c]);
                vv2 [jj*4+c] = *(const __half2*)&pv[c];
            }
        }
    }

    // prologue: stage k-group 0 (4 rows x 2KB = 512 uint4, 4 per thread)
    #pragma unroll
    for (int p=0;p<4;p++){
        int f = t + p*128;
        int row = f >> 7, c16 = f & 127;
        cp16(&spk[0][row][c16*8],
             g_pk_h + (size_t)((kc*32 + row)*BATCH + b)*N_DIM + c16*8);
    }
    asm volatile("cp.async.commit_group;");

    float s_all[32];

    #pragma unroll
    for (int kg = 0; kg < 8; kg++){
        int cur = kg & 1;
        asm volatile("cp.async.wait_group 0;");
        __syncthreads();
        if (kg + 1 < 8){
            #pragma unroll
            for (int p=0;p<4;p++){
                int f = t + p*128;
                int row = f >> 7, c16 = f & 127;
                cp16(&spk[cur^1][row][c16*8],
                     g_pk_h + (size_t)((kc*32 + (kg+1)*4 + row)*BATCH + b)*N_DIM + c16*8);
            }
            asm volatile("cp.async.commit_group;");
        }

        #pragma unroll
        for (int kk=0;kk<4;kk++){
            const uint4* sp = (const uint4*)spk[cur][kk];
            __half2 a0 = __float2half2_rn(0.f), a1 = a0, a2 = a0, a3 = a0;
            #pragma unroll
            for (int jj=0;jj<4;jj++){
                uint4 u = sp[lane + 32*jj];
                const uint32_t* pu = &u.x;
                a0 = __hfma2(vv2[jj*4+0], tanh2(__hadd2(pqb2[jj*4+0], *(const __half2*)&pu[0])), a0);
                a1 = __hfma2(vv2[jj*4+1], tanh2(__hadd2(pqb2[jj*4+1], *(const __half2*)&pu[1])), a1);
                a2 = __hfma2(vv2[jj*4+2], tanh2(__hadd2(pqb2[jj*4+2], *(const __half2*)&pu[2])), a2);
                a3 = __hfma2(vv2[jj*4+3], tanh2(__hadd2(pqb2[jj*4+3], *(const __half2*)&pu[3])), a3);
            }
            __half2 s2 = __hadd2(__hadd2(a0,a1), __hadd2(a2,a3));
            s_all[kg*4 + kk] = __low2float(s2) + __high2float(s2);
        }
    }

    // all warps done reading pk -> safe to repurpose smem as transpose scratch
    __syncthreads();
    {
        float* tw = (float*)smem_raw + w*1024;   // 4KB per warp
        // write phase: lane writes partial p at [p*32 + (lane+p)&31] (conflict-free)
        #pragma unroll
        for (int p=0;p<32;p++)
            tw[p*32 + ((lane + p) & 31)] = s_all[p];
        __syncwarp();
        // read phase: lane j sums row j (entry i stored by lane i at (i+j)&31)
        float tot = 0.f;
        #pragma unroll
        for (int i=0;i<32;i++)
            tot += tw[lane*32 + ((i + lane) & 31)];
        // coalesced: consecutive lanes -> consecutive k
        g_sraw[(size_t)r*TK + kc*32 + lane] = tot;
    }
}

// ---------------- softmax + context ----------------
// grid (8 q-tiles of 8, 32 batches), 256 threads. Warp w owns q = qt*8+w.
__global__ void __launch_bounds__(256) softmax_ctx_kernel(const float* __restrict__ keys,
                                                          float* __restrict__ out_ctx,
                                                          float* __restrict__ out_scores){
    __shared__ float sw[8][TK];
    int t = threadIdx.x, w = t >> 5, lane = t & 31;
    int qt = blockIdx.x, b = blockIdx.y;
    int r = (qt*8 + w)*BATCH + b;

    float sc[4];
    #pragma unroll
    for (int j=0;j<4;j++) sc[j] = g_sraw[(size_t)r*TK + lane + 32*j];
    float mx = fmaxf(fmaxf(sc[0],sc[1]), fmaxf(sc[2],sc[3]));
    #pragma unroll
    for (int off=16; off; off>>=1) mx = fmaxf(mx, __shfl_xor_sync(0xffffffffu, mx, off));
    float sum = 0.f;
    #pragma unroll
    for (int j=0;j<4;j++){ sc[j] = __expf(sc[j]-mx); sum += sc[j]; }
    #pragma unroll
    for (int off=16; off; off>>=1) sum += __shfl_xor_sync(0xffffffffu, sum, off);
    float inv = 1.f/sum;
    #pragma unroll
    for (int j=0;j<4;j++){
        float wk = sc[j]*inv;
        sw[w][lane + 32*j] = wk;
        out_scores[(size_t)r*TK + lane + 32*j] = wk;
    }
    __syncthreads();

    // context: ctx[q][nn] = sum_k w[q][k] * keys[k][b][nn]
    float4 acc[8];
    #pragma unroll
    for (int q8=0;q8<8;q8++) acc[q8] = make_float4(0.f,0.f,0.f,0.f);
    #pragma unroll 4
    for (int k=0;k<TK;k++){
        float4 kv = ((const float4*)(keys + (size_t)(k*BATCH + b)*N_DIM))[t];
        #pragma unroll
        for (int q8=0;q8<8;q8++){
            float wk = sw[q8][k];
            acc[q8].x += wk*kv.x; acc[q8].y += wk*kv.y;
            acc[q8].z += wk*kv.z; acc[q8].w += wk*kv.w;
        }
    }
    #pragma unroll
    for (int q8=0;q8<8;q8++){
        int rr = (qt*8 + q8)*BATCH + b;
        ((float4*)(out_ctx + (size_t)rr*N_DIM))[t] = acc[q8];
    }
}

// ---------------- launch ----------------
extern "C" void kernel_launch(void* const* d_in, const int* in_sizes, int n_in,
                              void* d_out, int out_size){
    const float* query = (const float*)d_in[0];
    const float* keys  = (const float*)d_in[1];
    const float* Wq    = (const float*)d_in[2];
    const float* Wk    = (const float*)d_in[3];
    const float* la    = (const float*)d_in[4];
    const float* ns    = (const float*)d_in[5];
    const float* bias  = (const float*)d_in[6];

    float* out_ctx    = (float*)d_out;
    float* out_scores = (float*)d_out + (size_t)MQ*N_DIM;

    conv_all_kernel<<<2048,256>>>(query, keys, Wq, Wk);
    prep_v_kernel<<<1,256>>>(la, ns, bias);

    gemm_kernel<<<dim3(48, 8), 256>>>();

    score_raw_kernel<<<dim3(16, BATCH, 4), 128>>>();
    softmax_ctx_kernel<<<dim3(8, BATCH), 256>>>(keys, out_ctx, out_scores);
}